// round 2
// baseline (speedup 1.0000x reference)
#include <cuda_runtime.h>
#include <cuda_bf16.h>

// GaussianBlurND: y = depthwise_blur9x9(x) / blur9x9(ones)
// Separable: f[i][j] = a[i]*a[j], a = row-sums of normalized 2D filter.
// Edge weight factorizes -> per-row and per-col renormalization.
// Fused single kernel: vertical conv (GMEM->regs->SMEM), horizontal conv
// (SMEM float4 -> GMEM float4).

#define HW   256
#define KS   9
#define PADR 4
#define TH   32           // rows per block strip
#define TPITCH 264        // tmp row pitch: 4 zero cols + 256 data + 4 zero cols

__global__ __launch_bounds__(256)
void gauss_blur_norm_kernel(const float* __restrict__ x,
                            const float* __restrict__ filt,
                            float* __restrict__ out)
{
    __shared__ float a_s[16];
    __shared__ float tmp_s[TH * TPITCH];   // 33792 B

    const int tid   = threadIdx.x;
    const int plane = blockIdx.y;
    const int r0    = blockIdx.x * TH;

    const float* xp = x   + (size_t)plane * (HW * HW);
    float*       op = out + (size_t)plane * (HW * HW);

    // --- separable filter taps: a[i] = sum_j filt[0][0][i][j]  (sum = 1) ---
    if (tid < KS) {
        float s = 0.f;
        #pragma unroll
        for (int j = 0; j < KS; j++) s += filt[tid * KS + j];
        a_s[tid] = s;
    }
    // zero-pad the left/right borders of tmp (8 cols x TH rows = 256 entries)
    {
        int r = tid >> 3, b = tid & 7;
        int cc = (b < 4) ? b : (260 + (b - 4));
        tmp_s[r * TPITCH + cc] = 0.f;
    }
    __syncthreads();

    float a[KS];
    #pragma unroll
    for (int i = 0; i < KS; i++) a[i] = a_s[i];

    // ---------------- Phase 1: vertical conv, column per thread ------------
    // rolling 9-row register window; coalesced LDG.32 across the warp
    {
        const int w = tid;  // 256 threads == 256 columns
        float win[KS];
        #pragma unroll
        for (int i = 0; i < 8; i++) {
            int gr = r0 - PADR + i;
            win[i] = (gr >= 0 && gr < HW) ? xp[gr * HW + w] : 0.f;
        }
        #pragma unroll
        for (int r = 0; r < TH; r++) {
            int grn = r0 + r + PADR;
            win[8] = (grn < HW) ? xp[grn * HW + w] : 0.f;

            float s = 0.f;
            #pragma unroll
            for (int i = 0; i < KS; i++) s += a[i] * win[i];

            int gh = r0 + r;
            float inv = 1.f;
            if (gh < PADR || gh >= HW - PADR) {
                float hs = 0.f;
                #pragma unroll
                for (int i = 0; i < KS; i++) {
                    int src = gh + i - PADR;
                    if (src >= 0 && src < HW) hs += a[i];
                }
                inv = 1.f / hs;
            }
            tmp_s[r * TPITCH + PADR + w] = s * inv;

            #pragma unroll
            for (int i = 0; i < 8; i++) win[i] = win[i + 1];
        }
    }
    __syncthreads();

    // ---------------- Phase 2: horizontal conv, 4 cols per thread ----------
    // thread t: column group c4 = t & 63 (cols 4*c4 .. 4*c4+3), row stride 4
    {
        const int c4   = tid & 63;
        const int rsub = tid >> 6;
        const int wbase = c4 * 4;

        // per-column renorm (only first/last group is non-trivial)
        float winv[4];
        #pragma unroll
        for (int c = 0; c < 4; c++) {
            int gw = wbase + c;
            float v = 1.f;
            if (gw < PADR || gw >= HW - PADR) {
                float ws = 0.f;
                #pragma unroll
                for (int j = 0; j < KS; j++) {
                    int src = gw + j - PADR;
                    if (src >= 0 && src < HW) ws += a[j];
                }
                v = 1.f / ws;
            }
            winv[c] = v;
        }

        #pragma unroll
        for (int r = rsub; r < TH; r += 4) {
            // need data cols [wbase-4 .. wbase+7] = smem idx [wbase .. wbase+11]
            const float4* src = (const float4*)(tmp_s + r * TPITCH + wbase);
            float4 v0 = src[0], v1 = src[1], v2 = src[2];
            float v[12] = { v0.x, v0.y, v0.z, v0.w,
                            v1.x, v1.y, v1.z, v1.w,
                            v2.x, v2.y, v2.z, v2.w };
            float4 o;
            float s;
            s = 0.f;
            #pragma unroll
            for (int j = 0; j < KS; j++) s += a[j] * v[0 + j];
            o.x = s * winv[0];
            s = 0.f;
            #pragma unroll
            for (int j = 0; j < KS; j++) s += a[j] * v[1 + j];
            o.y = s * winv[1];
            s = 0.f;
            #pragma unroll
            for (int j = 0; j < KS; j++) s += a[j] * v[2 + j];
            o.z = s * winv[2];
            s = 0.f;
            #pragma unroll
            for (int j = 0; j < KS; j++) s += a[j] * v[3 + j];
            o.w = s * winv[3];

            *(float4*)(op + (size_t)(r0 + r) * HW + wbase) = o;
        }
    }
}

extern "C" void kernel_launch(void* const* d_in, const int* in_sizes, int n_in,
                              void* d_out, int out_size)
{
    // Identify inputs by size (x = N*C*H*W, filt = C*1*9*9) — robust to order.
    const float* x    = (const float*)d_in[0];
    const float* filt = (const float*)d_in[1];
    if (n_in >= 2 && in_sizes[0] < in_sizes[1]) {
        x    = (const float*)d_in[1];
        filt = (const float*)d_in[0];
    }
    float* out = (float*)d_out;

    int planes = out_size / (HW * HW);      // N*C = 1024
    dim3 grid(HW / TH, planes);
    gauss_blur_norm_kernel<<<grid, 256>>>(x, filt, out);
}

// round 4
// speedup vs baseline: 1.5807x; 1.5807x over previous
#include <cuda_runtime.h>
#include <cuda_bf16.h>

// GaussianBlurND: y = depthwise_blur9x9(x) / blur9x9(ones)
// Separable: f[i][j] = a[i]*a[j], a = row-sums of normalized 2D filter.
// Edge weight factorizes -> per-row and per-col renormalization.
//
// R3 (resubmit; infra failed last round): latency-bound fix. Front-batched
// float4 tile load (MLP~10/thread) into smem, vertical conv computed
// IN-PLACE in smem (column-owner threads, no extra buffer), horizontal conv
// LDS.128 -> STG.128.

#define HW     256
#define KS     9
#define PADR   4
#define TH     32            // output rows per block strip
#define TROWS  (TH + 2*PADR) // 40 input rows incl. halo
#define TPITCH 264           // 4 zero cols + 256 data + 4 zero cols

__global__ __launch_bounds__(256)
void gauss_blur_norm_kernel(const float* __restrict__ x,
                            const float* __restrict__ filt,
                            float* __restrict__ out)
{
    __shared__ float a_s[16];
    __shared__ float xs[TROWS * TPITCH];   // 42240 B

    const int tid   = threadIdx.x;
    const int plane = blockIdx.y;
    const int r0    = blockIdx.x * TH;

    const float* xp = x   + (size_t)plane * (HW * HW);
    float*       op = out + (size_t)plane * (HW * HW);

    // --- separable taps: a[i] = sum_j filt[i][j]  (sum over 2D filter = 1) ---
    if (tid < KS) {
        float s = 0.f;
        #pragma unroll
        for (int j = 0; j < KS; j++) s += filt[tid * KS + j];
        a_s[tid] = s;
    }

    // --- zero left/right pad columns (rows 0..39, 8 cols each) ---
    for (int k = tid; k < TROWS * 8; k += 256) {
        int r = k >> 3, b = k & 7;
        int cc = (b < 4) ? b : (260 + (b - 4));
        xs[r * TPITCH + cc] = 0.f;
    }

    // --- front-batched tile load: 40 rows x 64 float4, 10 indep LDG.128/thread
    {
        const float4 z4 = make_float4(0.f, 0.f, 0.f, 0.f);
        #pragma unroll
        for (int it = 0; it < (TROWS * 64) / 256; it++) {
            int k  = it * 256 + tid;
            int i  = k >> 6;          // tile row 0..39
            int cg = k & 63;          // float4 group 0..63
            int gr = r0 - PADR + i;
            float4 v = (gr >= 0 && gr < HW)
                     ? *(const float4*)(xp + (size_t)gr * HW + cg * 4)
                     : z4;
            *(float4*)(xs + i * TPITCH + PADR + cg * 4) = v;
        }
    }
    __syncthreads();

    float a[KS];
    #pragma unroll
    for (int i = 0; i < KS; i++) a[i] = a_s[i];

    // ---------------- vertical conv, IN-PLACE in smem ----------------------
    // thread = one column; rolling 9-reg window. Each thread reads and writes
    // only its own column, and row r is dead (for this column) once output r
    // is written -> no intra-phase sync needed.
    {
        const int w = tid;
        float win[KS];
        #pragma unroll
        for (int i = 0; i < 8; i++)
            win[i] = xs[i * TPITCH + PADR + w];

        #pragma unroll
        for (int r = 0; r < TH; r++) {
            win[8] = xs[(r + 8) * TPITCH + PADR + w];

            float s = 0.f;
            #pragma unroll
            for (int i = 0; i < KS; i++) s += a[i] * win[i];

            int gh = r0 + r;
            float inv = 1.f;
            if (gh < PADR || gh >= HW - PADR) {
                float hs = 0.f;
                #pragma unroll
                for (int i = 0; i < KS; i++) {
                    int src = gh + i - PADR;
                    if (src >= 0 && src < HW) hs += a[i];
                }
                inv = 1.f / hs;
            }
            xs[r * TPITCH + PADR + w] = s * inv;

            #pragma unroll
            for (int i = 0; i < 8; i++) win[i] = win[i + 1];
        }
    }
    __syncthreads();

    // ---------------- horizontal conv: 4 cols/thread, LDS.128 window --------
    {
        const int c4    = tid & 63;
        const int rsub  = tid >> 6;
        const int wbase = c4 * 4;

        float winv[4];
        #pragma unroll
        for (int c = 0; c < 4; c++) {
            int gw = wbase + c;
            float v = 1.f;
            if (gw < PADR || gw >= HW - PADR) {
                float ws = 0.f;
                #pragma unroll
                for (int j = 0; j < KS; j++) {
                    int src = gw + j - PADR;
                    if (src >= 0 && src < HW) ws += a[j];
                }
                v = 1.f / ws;
            }
            winv[c] = v;
        }

        #pragma unroll
        for (int r = rsub; r < TH; r += 4) {
            const float4* src = (const float4*)(xs + r * TPITCH + wbase);
            float4 v0 = src[0], v1 = src[1], v2 = src[2];
            float v[12] = { v0.x, v0.y, v0.z, v0.w,
                            v1.x, v1.y, v1.z, v1.w,
                            v2.x, v2.y, v2.z, v2.w };
            float4 o;
            float s;
            s = 0.f;
            #pragma unroll
            for (int j = 0; j < KS; j++) s += a[j] * v[0 + j];
            o.x = s * winv[0];
            s = 0.f;
            #pragma unroll
            for (int j = 0; j < KS; j++) s += a[j] * v[1 + j];
            o.y = s * winv[1];
            s = 0.f;
            #pragma unroll
            for (int j = 0; j < KS; j++) s += a[j] * v[2 + j];
            o.z = s * winv[2];
            s = 0.f;
            #pragma unroll
            for (int j = 0; j < KS; j++) s += a[j] * v[3 + j];
            o.w = s * winv[3];

            *(float4*)(op + (size_t)(r0 + r) * HW + wbase) = o;
        }
    }
}

extern "C" void kernel_launch(void* const* d_in, const int* in_sizes, int n_in,
                              void* d_out, int out_size)
{
    // Identify inputs by size (x = N*C*H*W, filt = C*1*9*9) — robust to order.
    const float* x    = (const float*)d_in[0];
    const float* filt = (const float*)d_in[1];
    if (n_in >= 2 && in_sizes[0] < in_sizes[1]) {
        x    = (const float*)d_in[1];
        filt = (const float*)d_in[0];
    }
    float* out = (float*)d_out;

    int planes = out_size / (HW * HW);      // N*C = 1024
    dim3 grid(HW / TH, planes);
    gauss_blur_norm_kernel<<<grid, 256>>>(x, filt, out);
}